// round 1
// baseline (speedup 1.0000x reference)
#include <cuda_runtime.h>

#define F    128      // HID == F_IN
#define H    8        // heads
#define DH   16       // dim per head
#define NMAX 50000
#define EMAX 850000

// ---------------- device scratch (no allocations allowed) ----------------
__device__ __align__(16) float g_xc[NMAX * F];      // running node features
__device__ __align__(16) float g_h[NMAX * F];       // per-layer projected features
__device__ __align__(16) float g_asrc[NMAX * H];
__device__ __align__(16) float g_adst[NMAX * H];
__device__ __align__(16) float g_rowsum[NMAX * H];
__device__ __align__(16) float g_agg[NMAX * F];
__device__ __align__(16) float g_Wflat[F * F];      // [k][h*16+f]

// ---------------- helpers ----------------
__device__ __forceinline__ void red_add_v4(float* addr, float a, float b, float c, float d) {
    asm volatile("red.global.add.v4.f32 [%0], {%1,%2,%3,%4};"
                 :: "l"(addr), "f"(a), "f"(b), "f"(c), "f"(d) : "memory");
}

// ---------------- W transpose: [H][128][16] -> [128][128] ----------------
__global__ void transposeW_kernel(const float* __restrict__ W, float* __restrict__ Wf) {
    int idx = blockIdx.x * blockDim.x + threadIdx.x;   // 16384 threads
    if (idx >= F * F) return;
    int k = idx >> 7;
    int c = idx & 127;
    int hh = c >> 4, f = c & 15;
    Wf[idx] = W[(hh * F + k) * DH + f];
}

// ---------------- SGEMM: C[N,128] = A[N,128] @ B[128,128] (+bias) ----------------
// block = 64 rows x 128 cols, 256 threads (16x16), K chunked by 32.
__global__ void gemm128_kernel(const float* __restrict__ A, const float* __restrict__ B,
                               const float* __restrict__ bias, float* __restrict__ C, int N) {
    __shared__ float As[64][33];
    __shared__ float Bs[32][128];
    int tid = threadIdx.x;
    int tx = tid & 15, ty = tid >> 4;
    int row0 = blockIdx.x * 64;

    float acc[4][8];
#pragma unroll
    for (int i = 0; i < 4; i++)
#pragma unroll
        for (int j = 0; j < 8; j++) acc[i][j] = 0.f;

    for (int k0 = 0; k0 < F; k0 += 32) {
#pragma unroll
        for (int i = 0; i < 8; i++) {               // 64x32 A tile
            int lin = tid + i * 256;
            int r = lin >> 5, k = lin & 31;
            float v = 0.f;
            if (row0 + r < N) v = A[(row0 + r) * F + k0 + k];
            As[r][k] = v;
        }
#pragma unroll
        for (int i = 0; i < 16; i++) {              // 32x128 B tile
            int lin = tid + i * 256;
            int kk = lin >> 7, c = lin & 127;
            Bs[kk][c] = B[(k0 + kk) * F + c];
        }
        __syncthreads();
#pragma unroll
        for (int kk = 0; kk < 32; kk++) {
            float bv[8], av[4];
#pragma unroll
            for (int j = 0; j < 8; j++) bv[j] = Bs[kk][tx + j * 16];
#pragma unroll
            for (int i = 0; i < 4; i++) av[i] = As[ty * 4 + i][kk];
#pragma unroll
            for (int i = 0; i < 4; i++)
#pragma unroll
                for (int j = 0; j < 8; j++) acc[i][j] += av[i] * bv[j];
        }
        __syncthreads();
    }
#pragma unroll
    for (int i = 0; i < 4; i++) {
        int r = row0 + ty * 4 + i;
        if (r < N) {
#pragma unroll
            for (int j = 0; j < 8; j++) {
                int c = tx + j * 16;
                float v = acc[i][j];
                if (bias) v += bias[c];
                C[r * F + c] = v;
            }
        }
    }
}

// ---------------- per-node attention coefficients ----------------
__global__ void alpha_kernel(const float* __restrict__ hfeat, const float* __restrict__ a,
                             float* __restrict__ asrc, float* __restrict__ adst, int N) {
    int idx = blockIdx.x * blockDim.x + threadIdx.x;   // n*8 + h
    if (idx >= N * H) return;
    int hh = idx & 7;
    const float4* hp = (const float4*)(hfeat + (idx >> 3) * F + hh * DH);
    const float* av = a + hh * 2 * DH;
    float s = 0.f, d = 0.f;
#pragma unroll
    for (int j = 0; j < 4; j++) {
        float4 v = hp[j];
        s += v.x * __ldg(av + j * 4 + 0) + v.y * __ldg(av + j * 4 + 1)
           + v.z * __ldg(av + j * 4 + 2) + v.w * __ldg(av + j * 4 + 3);
        d += v.x * __ldg(av + 16 + j * 4 + 0) + v.y * __ldg(av + 16 + j * 4 + 1)
           + v.z * __ldg(av + 16 + j * 4 + 2) + v.w * __ldg(av + 16 + j * 4 + 3);
    }
    asrc[idx] = s;
    adst[idx] = d;
}

// ---------------- zero agg + rowsum ----------------
__global__ void clear_kernel(float* __restrict__ agg, float* __restrict__ rowsum, int N) {
    int idx = blockIdx.x * blockDim.x + threadIdx.x;
    if (idx < N * F) agg[idx] = 0.f;
    else if (idx < N * F + N * H) rowsum[idx - N * F] = 0.f;
}

// ---------------- edge scatter: the sparse core ----------------
__global__ void edge_kernel(const int* __restrict__ row, const int* __restrict__ col,
                            const float* __restrict__ ev,
                            const float* __restrict__ asrc, const float* __restrict__ adst,
                            const float* __restrict__ hfeat,
                            float* __restrict__ rowsum, float* __restrict__ agg, int E) {
    int idx = blockIdx.x * blockDim.x + threadIdx.x;   // e*8 + h
    if (idx >= E * H) return;
    int e = idx >> 3, hh = idx & 7;
    int r = __ldg(row + e);
    int c = __ldg(col + e);
    float lg = __ldg(ev + e) * (__ldg(asrc + r * H + hh) + __ldg(adst + c * H + hh));
    lg = lg > 0.f ? lg : 0.2f * lg;                    // leaky_relu(0.2)
    float w = __expf(lg);
    atomicAdd(rowsum + r * H + hh, w);
    const float4* hp = (const float4*)(hfeat + c * F + hh * DH);
    float* ap = agg + r * F + hh * DH;
#pragma unroll
    for (int j = 0; j < 4; j++) {
        float4 v = hp[j];
        red_add_v4(ap + j * 4, w * v.x, w * v.y, w * v.z, w * v.w);
    }
}

// ---------------- normalize + activation / skip ----------------
__global__ void finalize_kernel(const float* __restrict__ agg, const float* __restrict__ rowsum,
                                const float* __restrict__ skip, float* __restrict__ out,
                                int N, int mode) {  // mode 0: elu, no skip | mode 1: +skip
    int idx = blockIdx.x * blockDim.x + threadIdx.x;
    if (idx >= N * F) return;
    int n = idx >> 7, hh = (idx >> 4) & 7;
    float v = agg[idx] / rowsum[n * H + hh];
    if (mode == 0) v = (v > 0.f) ? v : expm1f(v);
    else v += skip[idx];
    out[idx] = v;
}

// ---------------- launch ----------------
extern "C" void kernel_launch(void* const* d_in, const int* in_sizes, int n_in,
                              void* d_out, int out_size) {
    const float* x    = (const float*)d_in[0];
    const int*   eidx = (const int*)  d_in[1];
    const float* ev   = (const float*)d_in[2];
    const float* encW = (const float*)d_in[3];
    const float* encb = (const float*)d_in[4];
    const float* Wst  = (const float*)d_in[5];
    const float* ast  = (const float*)d_in[6];
    float* out = (float*)d_out;

    int N = in_sizes[0] / F;
    int E = in_sizes[2];
    const int* row = eidx;
    const int* colp = eidx + E;

    float *xc, *hbuf, *asrc, *adst, *rowsum, *agg, *Wf;
    cudaGetSymbolAddress((void**)&xc,     g_xc);
    cudaGetSymbolAddress((void**)&hbuf,   g_h);
    cudaGetSymbolAddress((void**)&asrc,   g_asrc);
    cudaGetSymbolAddress((void**)&adst,   g_adst);
    cudaGetSymbolAddress((void**)&rowsum, g_rowsum);
    cudaGetSymbolAddress((void**)&agg,    g_agg);
    cudaGetSymbolAddress((void**)&Wf,     g_Wflat);

    const int TB = 256;
    int gemm_blocks  = (N + 63) / 64;
    int alpha_blocks = (N * H + TB - 1) / TB;
    int clear_blocks = (N * F + N * H + TB - 1) / TB;
    int edge_blocks  = (E * H + TB - 1) / TB;
    int fin_blocks   = (N * F + TB - 1) / TB;

    // encoder: xc = x @ enc_W + enc_b
    gemm128_kernel<<<gemm_blocks, TB>>>(x, encW, encb, xc, N);

    for (int ell = 0; ell < 2; ell++) {
        const float* Wl = Wst + ell * H * F * DH;
        const float* al = ast + ell * H * 2 * DH;

        transposeW_kernel<<<(F * F + TB - 1) / TB, TB>>>(Wl, Wf);
        gemm128_kernel<<<gemm_blocks, TB>>>(xc, Wf, nullptr, hbuf, N);
        alpha_kernel<<<alpha_blocks, TB>>>(hbuf, al, asrc, adst, N);
        clear_kernel<<<clear_blocks, TB>>>(agg, rowsum, N);
        edge_kernel<<<edge_blocks, TB>>>(row, colp, ev, asrc, adst, hbuf, rowsum, agg, E);

        if (ell == 0) {
            // xc = elu(agg / rowsum)   (overwrite in place; h was already consumed)
            finalize_kernel<<<fin_blocks, TB>>>(agg, rowsum, nullptr, xc, N, 0);
        } else {
            // out = agg / rowsum + xc
            finalize_kernel<<<fin_blocks, TB>>>(agg, rowsum, xc, out, N, 1);
        }
    }
}

// round 2
// speedup vs baseline: 1.4747x; 1.4747x over previous
#include <cuda_runtime.h>

#define F     128      // HID == F_IN
#define H     8        // heads
#define DH    16       // dim per head
#define NMAX  65536
#define EMAX  1000000

// ---------------- device scratch (no allocations allowed) ----------------
__device__ __align__(16) float g_xc[NMAX * F];      // running node features
__device__ __align__(16) float g_h[NMAX * F];       // per-layer projected features
__device__ __align__(16) float g_asrc[NMAX * H];
__device__ __align__(16) float g_adst[NMAX * H];
__device__ __align__(16) float g_Wflat[F * F];      // [k][h*16+f]
__device__ int   g_cnt[NMAX];                       // degree histogram
__device__ int   g_offs[NMAX + 1];                  // CSR row offsets
__device__ int   g_cursor[NMAX];                    // scatter cursors
__device__ int   g_cols[EMAX];                      // CSR col indices
__device__ float g_evs[EMAX];                       // CSR edge values

// ---------------- W transpose: [H][128][16] -> [128][128] ----------------
__global__ void transposeW_kernel(const float* __restrict__ W, float* __restrict__ Wf) {
    int idx = blockIdx.x * blockDim.x + threadIdx.x;
    if (idx >= F * F) return;
    int k = idx >> 7;
    int c = idx & 127;
    int hh = c >> 4, f = c & 15;
    Wf[idx] = W[(hh * F + k) * DH + f];
}

// ---------------- SGEMM + fused alpha ----------------
// C[N,128] = A[N,128] @ B[128,128] (+bias). If avec != null, also computes
// asrc[n][h] = sum_f C[n][h*16+f]*avec[h*32+f], adst with avec[h*32+16+f].
// block = 64 rows x 128 cols, 256 threads (16x16). Thread (tx,ty) holds
// rows ty*4+i, columns tx + j*16 -> head j, intra-head dim tx.
__global__ __launch_bounds__(256)
void gemm128_kernel(const float* __restrict__ A, const float* __restrict__ B,
                    const float* __restrict__ bias, float* __restrict__ C,
                    const float* __restrict__ avec,
                    float* __restrict__ asrc, float* __restrict__ adst, int N) {
    __shared__ float As[64][33];
    __shared__ float Bs[32][128];
    int tid = threadIdx.x;
    int tx = tid & 15, ty = tid >> 4;
    int row0 = blockIdx.x * 64;

    float acc[4][8];
#pragma unroll
    for (int i = 0; i < 4; i++)
#pragma unroll
        for (int j = 0; j < 8; j++) acc[i][j] = 0.f;

    for (int k0 = 0; k0 < F; k0 += 32) {
#pragma unroll
        for (int i = 0; i < 8; i++) {               // 64x32 A tile
            int lin = tid + i * 256;
            int r = lin >> 5, k = lin & 31;
            float v = 0.f;
            if (row0 + r < N) v = A[(row0 + r) * F + k0 + k];
            As[r][k] = v;
        }
#pragma unroll
        for (int i = 0; i < 16; i++) {              // 32x128 B tile
            int lin = tid + i * 256;
            int kk = lin >> 7, c = lin & 127;
            Bs[kk][c] = B[(k0 + kk) * F + c];
        }
        __syncthreads();
#pragma unroll
        for (int kk = 0; kk < 32; kk++) {
            float bv[8], av[4];
#pragma unroll
            for (int j = 0; j < 8; j++) bv[j] = Bs[kk][tx + j * 16];
#pragma unroll
            for (int i = 0; i < 4; i++) av[i] = As[ty * 4 + i][kk];
#pragma unroll
            for (int i = 0; i < 4; i++)
#pragma unroll
                for (int j = 0; j < 8; j++) acc[i][j] += av[i] * bv[j];
        }
        __syncthreads();
    }

    // epilogue: store C
#pragma unroll
    for (int i = 0; i < 4; i++) {
        int r = row0 + ty * 4 + i;
        if (r < N) {
#pragma unroll
            for (int j = 0; j < 8; j++) {
                int c = tx + j * 16;
                float v = acc[i][j];
                if (bias) v += bias[c];
                C[r * F + c] = v;
            }
        }
    }

    // fused alpha: butterfly-reduce over the 16 tx lanes (two independent
    // 16-lane groups per warp; xor masks 1,2,4,8 keep them separate).
    if (avec) {
        float a_s[8], a_d[8];
#pragma unroll
        for (int j = 0; j < 8; j++) {
            a_s[j] = __ldg(avec + j * 32 + tx);
            a_d[j] = __ldg(avec + j * 32 + 16 + tx);
        }
#pragma unroll
        for (int i = 0; i < 4; i++) {
            int r = row0 + ty * 4 + i;
#pragma unroll
            for (int j = 0; j < 8; j++) {
                float s = acc[i][j] * a_s[j];
                float d = acc[i][j] * a_d[j];
#pragma unroll
                for (int m = 1; m < 16; m <<= 1) {
                    s += __shfl_xor_sync(0xffffffffu, s, m);
                    d += __shfl_xor_sync(0xffffffffu, d, m);
                }
                if (tx == 0 && r < N) {
                    asrc[r * H + j] = s;
                    adst[r * H + j] = d;
                }
            }
        }
    }
}

// ---------------- CSR construction ----------------
__global__ void zero_cnt_kernel(int* __restrict__ cnt, int N) {
    int i = blockIdx.x * blockDim.x + threadIdx.x;
    if (i < N) cnt[i] = 0;
}

__global__ void hist_kernel(const int* __restrict__ row, int* __restrict__ cnt, int E) {
    int e = blockIdx.x * blockDim.x + threadIdx.x;
    if (e < E) atomicAdd(cnt + __ldg(row + e), 1);
}

// single-block exclusive scan over N counts -> offs[0..N], cursor copy
__global__ __launch_bounds__(1024)
void scan_kernel(const int* __restrict__ cnt, int* __restrict__ offs,
                 int* __restrict__ cursor, int N) {
    __shared__ int sums[1024];
    int t = threadIdx.x;
    int per = (N + 1023) / 1024;
    int beg = t * per;
    int end = beg + per; if (end > N) end = N;
    int s = 0;
    for (int i = beg; i < end; i++) s += cnt[i];
    sums[t] = s;
    __syncthreads();
    // Hillis-Steele inclusive scan
    for (int off = 1; off < 1024; off <<= 1) {
        int v = (t >= off) ? sums[t - off] : 0;
        __syncthreads();
        sums[t] += v;
        __syncthreads();
    }
    int run = (t == 0) ? 0 : sums[t - 1];
    for (int i = beg; i < end; i++) {
        offs[i] = run;
        cursor[i] = run;
        run += cnt[i];
    }
    if (t == 1023) offs[N] = sums[1023];
}

__global__ void scatter_kernel(const int* __restrict__ row, const int* __restrict__ col,
                               const float* __restrict__ ev,
                               int* __restrict__ cursor,
                               int* __restrict__ cols, float* __restrict__ evs, int E) {
    int e = blockIdx.x * blockDim.x + threadIdx.x;
    if (e >= E) return;
    int p = atomicAdd(cursor + __ldg(row + e), 1);
    cols[p] = __ldg(col + e);
    evs[p] = __ldg(ev + e);
}

// ---------------- fused edge gather + normalize + activation/skip ----------------
// one warp per row; lane owns feature dims [lane*4, lane*4+4), head = lane>>2
__global__ __launch_bounds__(256)
void edge_csr_kernel(const int* __restrict__ offs, const int* __restrict__ cols,
                     const float* __restrict__ evs,
                     const float* __restrict__ asrc, const float* __restrict__ adst,
                     const float* __restrict__ hfeat,
                     const float* __restrict__ skip, float* __restrict__ out,
                     int N, int mode) {   // mode 0: elu | mode 1: +skip
    int gwid = (blockIdx.x * blockDim.x + threadIdx.x) >> 5;
    if (gwid >= N) return;
    int lane = threadIdx.x & 31;
    int head = lane >> 2;

    float asr = __ldg(asrc + gwid * H + head);
    int beg = __ldg(offs + gwid);
    int end = __ldg(offs + gwid + 1);

    float ax = 0.f, ay = 0.f, az = 0.f, aw = 0.f, wsum = 0.f;

    int e = beg;
#pragma unroll 1
    for (; e + 1 < end; e += 2) {
        int   c0 = __ldg(cols + e),     c1 = __ldg(cols + e + 1);
        float v0 = __ldg(evs + e),      v1 = __ldg(evs + e + 1);
        float d0 = __ldg(adst + c0 * H + head);
        float d1 = __ldg(adst + c1 * H + head);
        float4 h0 = *(const float4*)(hfeat + c0 * F + lane * 4);
        float4 h1 = *(const float4*)(hfeat + c1 * F + lane * 4);
        float l0 = v0 * (asr + d0); l0 = fmaxf(l0, 0.2f * l0);
        float l1 = v1 * (asr + d1); l1 = fmaxf(l1, 0.2f * l1);
        float w0 = __expf(l0), w1 = __expf(l1);
        ax += w0 * h0.x + w1 * h1.x;
        ay += w0 * h0.y + w1 * h1.y;
        az += w0 * h0.z + w1 * h1.z;
        aw += w0 * h0.w + w1 * h1.w;
        wsum += w0 + w1;
    }
    if (e < end) {
        int   c0 = __ldg(cols + e);
        float v0 = __ldg(evs + e);
        float d0 = __ldg(adst + c0 * H + head);
        float4 h0 = *(const float4*)(hfeat + c0 * F + lane * 4);
        float l0 = v0 * (asr + d0); l0 = fmaxf(l0, 0.2f * l0);
        float w0 = __expf(l0);
        ax += w0 * h0.x; ay += w0 * h0.y; az += w0 * h0.z; aw += w0 * h0.w;
        wsum += w0;
    }

    float inv = 1.0f / wsum;
    float4 v;
    v.x = ax * inv; v.y = ay * inv; v.z = az * inv; v.w = aw * inv;
    if (mode == 0) {
        v.x = (v.x > 0.f) ? v.x : expm1f(v.x);
        v.y = (v.y > 0.f) ? v.y : expm1f(v.y);
        v.z = (v.z > 0.f) ? v.z : expm1f(v.z);
        v.w = (v.w > 0.f) ? v.w : expm1f(v.w);
    } else {
        float4 sk = *(const float4*)(skip + gwid * F + lane * 4);
        v.x += sk.x; v.y += sk.y; v.z += sk.z; v.w += sk.w;
    }
    *(float4*)(out + gwid * F + lane * 4) = v;
}

// ---------------- launch ----------------
extern "C" void kernel_launch(void* const* d_in, const int* in_sizes, int n_in,
                              void* d_out, int out_size) {
    const float* x    = (const float*)d_in[0];
    const int*   eidx = (const int*)  d_in[1];
    const float* ev   = (const float*)d_in[2];
    const float* encW = (const float*)d_in[3];
    const float* encb = (const float*)d_in[4];
    const float* Wst  = (const float*)d_in[5];
    const float* ast  = (const float*)d_in[6];
    float* out = (float*)d_out;

    int N = in_sizes[0] / F;
    int E = in_sizes[2];
    const int* row  = eidx;
    const int* colp = eidx + E;

    float *xc, *hbuf, *asrc, *adst, *Wf, *evs;
    int *cnt, *offs, *cursor, *cols;
    cudaGetSymbolAddress((void**)&xc,     g_xc);
    cudaGetSymbolAddress((void**)&hbuf,   g_h);
    cudaGetSymbolAddress((void**)&asrc,   g_asrc);
    cudaGetSymbolAddress((void**)&adst,   g_adst);
    cudaGetSymbolAddress((void**)&Wf,     g_Wflat);
    cudaGetSymbolAddress((void**)&cnt,    g_cnt);
    cudaGetSymbolAddress((void**)&offs,   g_offs);
    cudaGetSymbolAddress((void**)&cursor, g_cursor);
    cudaGetSymbolAddress((void**)&cols,   g_cols);
    cudaGetSymbolAddress((void**)&evs,    g_evs);

    const int TB = 256;
    int gemm_blocks = (N + 63) / 64;
    int edge_blocks = (N * 32 + TB - 1) / TB;

    // ---- CSR build (once per call; reused by both layers) ----
    zero_cnt_kernel<<<(N + TB - 1) / TB, TB>>>(cnt, N);
    hist_kernel<<<(E + TB - 1) / TB, TB>>>(row, cnt, E);
    scan_kernel<<<1, 1024>>>(cnt, offs, cursor, N);
    scatter_kernel<<<(E + TB - 1) / TB, TB>>>(row, colp, ev, cursor, cols, evs, E);

    // ---- encoder: xc = x @ enc_W + enc_b ----
    gemm128_kernel<<<gemm_blocks, TB>>>(x, encW, encb, xc, nullptr, nullptr, nullptr, N);

    for (int ell = 0; ell < 2; ell++) {
        const float* Wl = Wst + ell * H * F * DH;
        const float* al = ast + ell * H * 2 * DH;

        transposeW_kernel<<<(F * F + TB - 1) / TB, TB>>>(Wl, Wf);
        // h = xc @ Wf, with fused asrc/adst
        gemm128_kernel<<<gemm_blocks, TB>>>(xc, Wf, nullptr, hbuf, al, asrc, adst, N);

        if (ell == 0) {
            // xc = elu(agg / rowsum)
            edge_csr_kernel<<<edge_blocks, TB>>>(offs, cols, evs, asrc, adst, hbuf,
                                                 nullptr, xc, N, 0);
        } else {
            // out = agg / rowsum + xc
            edge_csr_kernel<<<edge_blocks, TB>>>(offs, cols, evs, asrc, adst, hbuf,
                                                 xc, out, N, 1);
        }
    }
}

// round 3
// speedup vs baseline: 1.6321x; 1.1067x over previous
#include <cuda_runtime.h>

#define F     128      // HID == F_IN
#define H     8        // heads
#define DH    16       // dim per head
#define NMAX  65536
#define EMAX  1000000

typedef unsigned long long ull;

// ---------------- device scratch (no allocations allowed) ----------------
__device__ __align__(16) float g_xc[NMAX * F];      // running node features
__device__ __align__(16) float g_h[NMAX * F];       // per-layer projected features
__device__ __align__(16) float g_asrc[NMAX * H];
__device__ __align__(16) float g_adst[NMAX * H];
__device__ __align__(16) float g_Wflat[F * F];      // [k][h*16+f]
__device__ int   g_cnt[NMAX];                       // degree histogram
__device__ int   g_offs[NMAX + 1];                  // CSR row offsets
__device__ int   g_cursor[NMAX];                    // scatter cursors
__device__ int   g_cols[EMAX];                      // CSR col indices
__device__ float g_evs[EMAX];                       // CSR edge values

// ---------------- packed f32x2 helpers ----------------
__device__ __forceinline__ ull fma2(ull a, ull b, ull c) {
    ull d;
    asm("fma.rn.f32x2 %0, %1, %2, %3;" : "=l"(d) : "l"(a), "l"(b), "l"(c));
    return d;
}
__device__ __forceinline__ ull pack2(float x, float y) {
    ull u;
    asm("mov.b64 %0, {%1, %2};" : "=l"(u) : "f"(x), "f"(y));
    return u;
}
__device__ __forceinline__ void unpack2(ull u, float& x, float& y) {
    asm("mov.b64 {%0, %1}, %2;" : "=f"(x), "=f"(y) : "l"(u));
}

// ---------------- W transpose: [H][128][16] -> [128][128] ----------------
__global__ void transposeW_kernel(const float* __restrict__ W, float* __restrict__ Wf) {
    int idx = blockIdx.x * blockDim.x + threadIdx.x;
    if (idx >= F * F) return;
    int k = idx >> 7;
    int c = idx & 127;
    int hh = c >> 4, f = c & 15;
    Wf[idx] = W[(hh * F + k) * DH + f];
}

// ---------------- packed SGEMM + fused alpha ----------------
// C[N,128] = A[N,128] @ B[128,128] (+bias), fp32 via fma.rn.f32x2.
// block tile 64 rows x 128 cols, 128 threads. tx = tid&15, ty = tid>>4 (0..7).
// Thread owns rows ty*8+i (i=0..7), packed col pairs c0(j) = j*32 + 2*tx, j=0..3.
// If avec != null: asrc[n][h] = sum_f C[n][h*16+f]*avec[h*32+f] (adst at +16).
__global__ __launch_bounds__(128)
void gemm128_kernel(const float* __restrict__ A, const float* __restrict__ B,
                    const float* __restrict__ bias, float* __restrict__ C,
                    const float* __restrict__ avec,
                    float* __restrict__ asrc, float* __restrict__ adst, int N) {
    __shared__ ull   As2[64][32];    // A tile, each value duplicated (v,v)
    __shared__ float Bs[32][128];
    int tid = threadIdx.x;
    int tx = tid & 15, ty = tid >> 4;
    int row0 = blockIdx.x * 64;

    ull acc[8][4];
#pragma unroll
    for (int i = 0; i < 8; i++)
#pragma unroll
        for (int j = 0; j < 4; j++) acc[i][j] = 0ull;

#pragma unroll 1
    for (int k0 = 0; k0 < F; k0 += 32) {
        // A tile 64x32 (2048 elems, 16/thread), duplicated into 8-byte words
#pragma unroll
        for (int i = 0; i < 16; i++) {
            int lin = tid + i * 128;
            int r = lin >> 5, k = lin & 31;
            float v = 0.f;
            if (row0 + r < N) v = A[(row0 + r) * F + k0 + k];
            As2[r][k] = pack2(v, v);
        }
        // B tile 32x128 (4096 elems, 32/thread)
#pragma unroll
        for (int i = 0; i < 32; i++) {
            int lin = tid + i * 128;
            int kk = lin >> 7, c = lin & 127;
            Bs[kk][c] = B[(k0 + kk) * F + c];
        }
        __syncthreads();
#pragma unroll 8
        for (int kk = 0; kk < 32; kk++) {
            ull bv[4], av[8];
#pragma unroll
            for (int j = 0; j < 4; j++)
                bv[j] = *(const ull*)&Bs[kk][j * 32 + 2 * tx];
#pragma unroll
            for (int i = 0; i < 8; i++) av[i] = As2[ty * 8 + i][kk];
#pragma unroll
            for (int i = 0; i < 8; i++)
#pragma unroll
                for (int j = 0; j < 4; j++)
                    acc[i][j] = fma2(av[i], bv[j], acc[i][j]);
        }
        __syncthreads();
    }

    // epilogue: (+bias) and store C as 8-byte words
#pragma unroll
    for (int i = 0; i < 8; i++) {
        int r = row0 + ty * 8 + i;
        if (r < N) {
#pragma unroll
            for (int j = 0; j < 4; j++) {
                int c0 = j * 32 + 2 * tx;
                float lo, hi;
                unpack2(acc[i][j], lo, hi);
                if (bias) { lo += __ldg(bias + c0); hi += __ldg(bias + c0 + 1); }
                float2 v; v.x = lo; v.y = hi;
                *(float2*)(C + r * F + c0) = v;
            }
        }
    }

    // fused alpha: head h(j) = j*2 + (tx>>3); cols f0 = 2*(tx&7), f0+1.
    // 8-lane xor-butterflies (masks 1,2,4) reduce each head group.
    if (avec) {
        float as0[4], as1[4], ad0[4], ad1[4];
        int f0 = 2 * (tx & 7);
#pragma unroll
        for (int j = 0; j < 4; j++) {
            int h = j * 2 + (tx >> 3);
            as0[j] = __ldg(avec + h * 32 + f0);
            as1[j] = __ldg(avec + h * 32 + f0 + 1);
            ad0[j] = __ldg(avec + h * 32 + 16 + f0);
            ad1[j] = __ldg(avec + h * 32 + 16 + f0 + 1);
        }
#pragma unroll
        for (int i = 0; i < 8; i++) {
            int r = row0 + ty * 8 + i;
#pragma unroll
            for (int j = 0; j < 4; j++) {
                float lo, hi;
                unpack2(acc[i][j], lo, hi);
                float s = lo * as0[j] + hi * as1[j];
                float d = lo * ad0[j] + hi * ad1[j];
#pragma unroll
                for (int m = 1; m < 8; m <<= 1) {
                    s += __shfl_xor_sync(0xffffffffu, s, m);
                    d += __shfl_xor_sync(0xffffffffu, d, m);
                }
                if ((tx & 7) == 0 && r < N) {
                    int h = j * 2 + (tx >> 3);
                    asrc[r * H + h] = s;
                    adst[r * H + h] = d;
                }
            }
        }
    }
}

// ---------------- CSR construction ----------------
__global__ void zero_cnt_kernel(int* __restrict__ cnt, int N) {
    int i = blockIdx.x * blockDim.x + threadIdx.x;
    if (i < N) cnt[i] = 0;
}

__global__ void hist_kernel(const int* __restrict__ row, int* __restrict__ cnt, int E) {
    int e = blockIdx.x * blockDim.x + threadIdx.x;
    if (e < E) atomicAdd(cnt + __ldg(row + e), 1);
}

// single-block exclusive scan over N counts -> offs[0..N], cursor copy
__global__ __launch_bounds__(1024)
void scan_kernel(const int* __restrict__ cnt, int* __restrict__ offs,
                 int* __restrict__ cursor, int N) {
    __shared__ int sums[1024];
    int t = threadIdx.x;
    int per = (N + 1023) / 1024;
    int beg = t * per;
    int end = beg + per; if (end > N) end = N;
    int s = 0;
    for (int i = beg; i < end; i++) s += cnt[i];
    sums[t] = s;
    __syncthreads();
    for (int off = 1; off < 1024; off <<= 1) {
        int v = (t >= off) ? sums[t - off] : 0;
        __syncthreads();
        sums[t] += v;
        __syncthreads();
    }
    int run = (t == 0) ? 0 : sums[t - 1];
    for (int i = beg; i < end; i++) {
        offs[i] = run;
        cursor[i] = run;
        run += cnt[i];
    }
    if (t == 1023) offs[N] = sums[1023];
}

__global__ void scatter_kernel(const int* __restrict__ row, const int* __restrict__ col,
                               const float* __restrict__ ev,
                               int* __restrict__ cursor,
                               int* __restrict__ cols, float* __restrict__ evs, int E) {
    int e = blockIdx.x * blockDim.x + threadIdx.x;
    if (e >= E) return;
    int p = atomicAdd(cursor + __ldg(row + e), 1);
    cols[p] = __ldg(col + e);
    evs[p] = __ldg(ev + e);
}

// ---------------- fused edge gather + normalize + activation/skip ----------------
// one warp per row; lane owns feature dims [lane*4, lane*4+4), head = lane>>2
__global__ __launch_bounds__(256)
void edge_csr_kernel(const int* __restrict__ offs, const int* __restrict__ cols,
                     const float* __restrict__ evs,
                     const float* __restrict__ asrc, const float* __restrict__ adst,
                     const float* __restrict__ hfeat,
                     const float* __restrict__ skip, float* __restrict__ out,
                     int N, int mode) {   // mode 0: elu | mode 1: +skip
    int gwid = (blockIdx.x * blockDim.x + threadIdx.x) >> 5;
    if (gwid >= N) return;
    int lane = threadIdx.x & 31;
    int head = lane >> 2;

    float asr = __ldg(asrc + gwid * H + head);
    int beg = __ldg(offs + gwid);
    int end = __ldg(offs + gwid + 1);

    float ax = 0.f, ay = 0.f, az = 0.f, aw = 0.f, wsum = 0.f;

    int e = beg;
#pragma unroll 1
    for (; e + 3 < end; e += 4) {
        int c[4]; float v[4], dd[4]; float4 hh[4];
#pragma unroll
        for (int q = 0; q < 4; q++) {
            c[q] = __ldg(cols + e + q);
            v[q] = __ldg(evs + e + q);
        }
#pragma unroll
        for (int q = 0; q < 4; q++) {
            dd[q] = __ldg(adst + c[q] * H + head);
            hh[q] = *(const float4*)(hfeat + c[q] * F + lane * 4);
        }
#pragma unroll
        for (int q = 0; q < 4; q++) {
            float l = v[q] * (asr + dd[q]);
            l = fmaxf(l, 0.2f * l);
            float w = __expf(l);
            ax += w * hh[q].x;
            ay += w * hh[q].y;
            az += w * hh[q].z;
            aw += w * hh[q].w;
            wsum += w;
        }
    }
#pragma unroll 1
    for (; e < end; e++) {
        int   c0 = __ldg(cols + e);
        float v0 = __ldg(evs + e);
        float d0 = __ldg(adst + c0 * H + head);
        float4 h0 = *(const float4*)(hfeat + c0 * F + lane * 4);
        float l0 = v0 * (asr + d0);
        l0 = fmaxf(l0, 0.2f * l0);
        float w0 = __expf(l0);
        ax += w0 * h0.x; ay += w0 * h0.y; az += w0 * h0.z; aw += w0 * h0.w;
        wsum += w0;
    }

    float inv = 1.0f / wsum;
    float4 v;
    v.x = ax * inv; v.y = ay * inv; v.z = az * inv; v.w = aw * inv;
    if (mode == 0) {
        v.x = (v.x > 0.f) ? v.x : expm1f(v.x);
        v.y = (v.y > 0.f) ? v.y : expm1f(v.y);
        v.z = (v.z > 0.f) ? v.z : expm1f(v.z);
        v.w = (v.w > 0.f) ? v.w : expm1f(v.w);
    } else {
        float4 sk = *(const float4*)(skip + gwid * F + lane * 4);
        v.x += sk.x; v.y += sk.y; v.z += sk.z; v.w += sk.w;
    }
    *(float4*)(out + gwid * F + lane * 4) = v;
}

// ---------------- launch ----------------
extern "C" void kernel_launch(void* const* d_in, const int* in_sizes, int n_in,
                              void* d_out, int out_size) {
    const float* x    = (const float*)d_in[0];
    const int*   eidx = (const int*)  d_in[1];
    const float* ev   = (const float*)d_in[2];
    const float* encW = (const float*)d_in[3];
    const float* encb = (const float*)d_in[4];
    const float* Wst  = (const float*)d_in[5];
    const float* ast  = (const float*)d_in[6];
    float* out = (float*)d_out;

    int N = in_sizes[0] / F;
    int E = in_sizes[2];
    const int* row  = eidx;
    const int* colp = eidx + E;

    float *xc, *hbuf, *asrc, *adst, *Wf, *evs;
    int *cnt, *offs, *cursor, *cols;
    cudaGetSymbolAddress((void**)&xc,     g_xc);
    cudaGetSymbolAddress((void**)&hbuf,   g_h);
    cudaGetSymbolAddress((void**)&asrc,   g_asrc);
    cudaGetSymbolAddress((void**)&adst,   g_adst);
    cudaGetSymbolAddress((void**)&Wf,     g_Wflat);
    cudaGetSymbolAddress((void**)&cnt,    g_cnt);
    cudaGetSymbolAddress((void**)&offs,   g_offs);
    cudaGetSymbolAddress((void**)&cursor, g_cursor);
    cudaGetSymbolAddress((void**)&cols,   g_cols);
    cudaGetSymbolAddress((void**)&evs,    g_evs);

    const int TB = 256;
    int gemm_blocks = (N + 63) / 64;
    int edge_blocks = (N * 32 + TB - 1) / TB;

    // ---- CSR build (once per call; reused by both layers) ----
    zero_cnt_kernel<<<(N + TB - 1) / TB, TB>>>(cnt, N);
    hist_kernel<<<(E + TB - 1) / TB, TB>>>(row, cnt, E);
    scan_kernel<<<1, 1024>>>(cnt, offs, cursor, N);
    scatter_kernel<<<(E + TB - 1) / TB, TB>>>(row, colp, ev, cursor, cols, evs, E);

    // ---- encoder: xc = x @ enc_W + enc_b ----
    gemm128_kernel<<<gemm_blocks, 128>>>(x, encW, encb, xc, nullptr, nullptr, nullptr, N);

    for (int ell = 0; ell < 2; ell++) {
        const float* Wl = Wst + ell * H * F * DH;
        const float* al = ast + ell * H * 2 * DH;

        transposeW_kernel<<<(F * F + TB - 1) / TB, TB>>>(Wl, Wf);
        // h = xc @ Wf, with fused asrc/adst
        gemm128_kernel<<<gemm_blocks, 128>>>(xc, Wf, nullptr, hbuf, al, asrc, adst, N);

        if (ell == 0) {
            edge_csr_kernel<<<edge_blocks, TB>>>(offs, cols, evs, asrc, adst, hbuf,
                                                 nullptr, xc, N, 0);
        } else {
            edge_csr_kernel<<<edge_blocks, TB>>>(offs, cols, evs, asrc, adst, hbuf,
                                                 xc, out, N, 1);
        }
    }
}

// round 6
// speedup vs baseline: 1.9777x; 1.2118x over previous
#include <cuda_runtime.h>
#include <cuda_bf16.h>
#include <cstdint>

#define F     128      // HID == F_IN
#define H     8        // heads
#define DH    16       // dim per head
#define NMAX  65536
#define EMAX  1000000

#define STR   136                       // padded bf16 row stride (272 B)
#define A_HI  0
#define A_LO  (128 * STR * 2)           // 34816
#define B_HI  (2 * 128 * STR * 2)       // 69632
#define B_LO  (3 * 128 * STR * 2)       // 104448
#define SMEM_TOT (4 * 128 * STR * 2)    // 139264

// ---------------- device scratch (no allocations allowed) ----------------
__device__ __align__(16) float g_xc[NMAX * F];
__device__ __align__(16) float g_h[NMAX * F];
__device__ __align__(16) float g_asrc[NMAX * H];
__device__ __align__(16) float g_adst[NMAX * H];
__device__ int   g_cnt[NMAX];
__device__ int   g_offs[NMAX + 1];
__device__ int   g_cursor[NMAX];
__device__ int   g_cols[EMAX];
__device__ float g_evs[EMAX];
// prepped weights: B^T [n][k] padded to STR, hi/lo bf16, 3 matrices
__device__ __align__(16) __nv_bfloat16 g_Bhi[3 * F * STR];
__device__ __align__(16) __nv_bfloat16 g_Blo[3 * F * STR];

// ---------------- helpers ----------------
__device__ __forceinline__ uint32_t smem_u32(const void* p) {
    uint32_t a;
    asm("{ .reg .u64 t; cvta.to.shared.u64 t, %1; cvt.u32.u64 %0, t; }" : "=r"(a) : "l"(p));
    return a;
}
__device__ __forceinline__ void ldx4(uint32_t* r, uint32_t addr) {
    asm volatile("ldmatrix.sync.aligned.m8n8.x4.shared.b16 {%0,%1,%2,%3}, [%4];"
                 : "=r"(r[0]), "=r"(r[1]), "=r"(r[2]), "=r"(r[3]) : "r"(addr));
}
__device__ __forceinline__ void mma_bf16(float* c, const uint32_t* a, uint32_t b0, uint32_t b1) {
    asm volatile("mma.sync.aligned.m16n8k16.row.col.f32.bf16.bf16.f32 "
                 "{%0,%1,%2,%3}, {%4,%5,%6,%7}, {%8,%9}, {%0,%1,%2,%3};"
                 : "+f"(c[0]), "+f"(c[1]), "+f"(c[2]), "+f"(c[3])
                 : "r"(a[0]), "r"(a[1]), "r"(a[2]), "r"(a[3]), "r"(b0), "r"(b1));
}

// ---------------- weight prep: W[k][n] -> B^T[n][k] padded, hi/lo bf16 ----------------
__global__ void prepB_kernel(const float* __restrict__ encW,
                             const float* __restrict__ Wst) {
    int idx = blockIdx.x * blockDim.x + threadIdx.x;
    if (idx >= 3 * F * STR) return;
    int mat = idx / (F * STR);
    int t = idx % (F * STR);
    int n = t / STR, k = t % STR;
    float w = 0.f;
    if (k < F) {
        if (mat == 0) w = encW[k * F + n];
        else {
            int hh = n >> 4, f = n & 15;
            w = Wst[(mat - 1) * (H * F * DH) + (hh * F + k) * DH + f];
        }
    }
    __nv_bfloat16 hi = __float2bfloat16(w);
    __nv_bfloat16 lo = __float2bfloat16(w - __bfloat162float(hi));
    g_Bhi[idx] = hi;
    g_Blo[idx] = lo;
}

// ---------------- HMMA GEMM: C[N,128] = A[N,128] @ W (+bias), fused alpha ----------------
// grid = ceil(N/128), 256 threads (8 warps). warp w: rows (w>>1)*32.., cols (w&1)*64..
// bf16 3-term split: Ahi*Bhi + Alo*Bhi + Ahi*Blo.
__global__ __launch_bounds__(256)
void mma_gemm_kernel(const float* __restrict__ A,
                     const __nv_bfloat16* __restrict__ Bhi,
                     const __nv_bfloat16* __restrict__ Blo,
                     const float* __restrict__ bias, float* __restrict__ C,
                     const float* __restrict__ avec,
                     float* __restrict__ asrc, float* __restrict__ adst, int Nrows) {
    extern __shared__ char smem[];
    uint32_t sb = smem_u32(smem);
    int tid = threadIdx.x;
    int l = tid & 31, w = tid >> 5;
    int row0 = blockIdx.x * 128;

    // ---- stage A: 128x128 f32 -> hi/lo bf16, padded rows ----
#pragma unroll
    for (int it = 0; it < 16; it++) {
        int g = tid + it * 256;
        int r = g >> 5;
        int kq = (g & 31) * 4;
        float4 v = make_float4(0.f, 0.f, 0.f, 0.f);
        if (row0 + r < Nrows) v = *(const float4*)(A + (size_t)(row0 + r) * F + kq);
        __nv_bfloat16 h0 = __float2bfloat16(v.x), h1 = __float2bfloat16(v.y);
        __nv_bfloat16 h2 = __float2bfloat16(v.z), h3 = __float2bfloat16(v.w);
        __nv_bfloat16 l0 = __float2bfloat16(v.x - __bfloat162float(h0));
        __nv_bfloat16 l1 = __float2bfloat16(v.y - __bfloat162float(h1));
        __nv_bfloat16 l2 = __float2bfloat16(v.z - __bfloat162float(h2));
        __nv_bfloat16 l3 = __float2bfloat16(v.w - __bfloat162float(h3));
        uint32_t off = (uint32_t)r * 272u + (uint32_t)kq * 2u;
        __nv_bfloat162 hp0 = {h0, h1}, hp1 = {h2, h3};
        __nv_bfloat162 lp0 = {l0, l1}, lp1 = {l2, l3};
        *(uint2*)(smem + A_HI + off) = make_uint2(*(uint32_t*)&hp0, *(uint32_t*)&hp1);
        *(uint2*)(smem + A_LO + off) = make_uint2(*(uint32_t*)&lp0, *(uint32_t*)&lp1);
    }
    // ---- copy prepped B^T hi/lo (34816 B each = 2176 uint4) ----
    for (int i = tid; i < 2176; i += 256) {
        ((uint4*)(smem + B_HI))[i] = ((const uint4*)Bhi)[i];
        ((uint4*)(smem + B_LO))[i] = ((const uint4*)Blo)[i];
    }
    __syncthreads();

    int wr = w >> 1, wc = w & 1;
    int lt = l & 7, lg = l >> 3;

    // ldmatrix lane-address offsets (bytes)
    uint32_t aoff[2];
#pragma unroll
    for (int i = 0; i < 2; i++)
        aoff[i] = (uint32_t)(wr * 32 + i * 16 + lt + (lg & 1) * 8) * 272u + (uint32_t)(lg >> 1) * 16u;
    uint32_t boff[4];
#pragma unroll
    for (int p = 0; p < 4; p++)
        boff[p] = (uint32_t)(wc * 64 + 8 * (2 * p + (lg >> 1)) + lt) * 272u + (uint32_t)(lg & 1) * 16u;

    float c[2][8][4];
#pragma unroll
    for (int i = 0; i < 2; i++)
#pragma unroll
        for (int j = 0; j < 8; j++)
#pragma unroll
            for (int q = 0; q < 4; q++) c[i][j][q] = 0.f;

    uint32_t ah[2][4], al[2][4], b[4][4];

#pragma unroll
    for (int ks = 0; ks < 8; ks++) {
        uint32_t k2 = (uint32_t)ks * 32u;   // 16 bf16 = 32 bytes
        ldx4(ah[0], sb + A_HI + aoff[0] + k2);
        ldx4(ah[1], sb + A_HI + aoff[1] + k2);
        ldx4(al[0], sb + A_LO + aoff[0] + k2);
        ldx4(al[1], sb + A_LO + aoff[1] + k2);
#pragma unroll
        for (int p = 0; p < 4; p++) ldx4(b[p], sb + B_HI + boff[p] + k2);
#pragma unroll
        for (int i = 0; i < 2; i++)
#pragma unroll
            for (int p = 0; p < 4; p++) {
                mma_bf16(c[i][2 * p],     ah[i], b[p][0], b[p][1]);
                mma_bf16(c[i][2 * p + 1], ah[i], b[p][2], b[p][3]);
                mma_bf16(c[i][2 * p],     al[i], b[p][0], b[p][1]);
                mma_bf16(c[i][2 * p + 1], al[i], b[p][2], b[p][3]);
            }
#pragma unroll
        for (int p = 0; p < 4; p++) ldx4(b[p], sb + B_LO + boff[p] + k2);
#pragma unroll
        for (int i = 0; i < 2; i++)
#pragma unroll
            for (int p = 0; p < 4; p++) {
                mma_bf16(c[i][2 * p],     ah[i], b[p][0], b[p][1]);
                mma_bf16(c[i][2 * p + 1], ah[i], b[p][2], b[p][3]);
            }
    }

    // ---- epilogue: store C (+bias), fused alpha ----
#pragma unroll
    for (int i = 0; i < 2; i++) {
#pragma unroll
        for (int rh = 0; rh < 2; rh++) {
            int row = row0 + wr * 32 + i * 16 + rh * 8 + (l >> 2);
            bool valid = (row < Nrows);
            if (valid) {
#pragma unroll
                for (int j = 0; j < 8; j++) {
                    int col = wc * 64 + 8 * j + 2 * (l & 3);
                    float v0 = c[i][j][2 * rh], v1 = c[i][j][2 * rh + 1];
                    if (bias) { v0 += __ldg(bias + col); v1 += __ldg(bias + col + 1); }
                    float2 st; st.x = v0; st.y = v1;
                    *(float2*)(C + (size_t)row * F + col) = st;
                }
            }
            if (avec) {
                float s[4], d[4];
#pragma unroll
                for (int q = 0; q < 4; q++) { s[q] = 0.f; d[q] = 0.f; }
#pragma unroll
                for (int j = 0; j < 8; j++) {
                    int hl = j >> 1;
                    int hh = 4 * wc + hl;
                    int f0 = 8 * (j & 1) + 2 * (l & 3);
                    float v0 = c[i][j][2 * rh], v1 = c[i][j][2 * rh + 1];
                    s[hl] += v0 * __ldg(avec + hh * 32 + f0) + v1 * __ldg(avec + hh * 32 + f0 + 1);
                    d[hl] += v0 * __ldg(avec + hh * 32 + 16 + f0) + v1 * __ldg(avec + hh * 32 + 16 + f0 + 1);
                }
#pragma unroll
                for (int q = 0; q < 4; q++) {
                    s[q] += __shfl_xor_sync(0xffffffffu, s[q], 1);
                    s[q] += __shfl_xor_sync(0xffffffffu, s[q], 2);
                    d[q] += __shfl_xor_sync(0xffffffffu, d[q], 1);
                    d[q] += __shfl_xor_sync(0xffffffffu, d[q], 2);
                }
                if ((l & 3) == 0 && valid) {
#pragma unroll
                    for (int q = 0; q < 4; q++) {
                        asrc[row * H + 4 * wc + q] = s[q];
                        adst[row * H + 4 * wc + q] = d[q];
                    }
                }
            }
        }
    }
}

// ---------------- CSR construction ----------------
__global__ void zero_cnt_kernel(int* __restrict__ cnt, int N) {
    int i = blockIdx.x * blockDim.x + threadIdx.x;
    if (i < N) cnt[i] = 0;
}
__global__ void hist_kernel(const int* __restrict__ row, int* __restrict__ cnt, int E) {
    int e = blockIdx.x * blockDim.x + threadIdx.x;
    if (e < E) atomicAdd(cnt + __ldg(row + e), 1);
}
__global__ __launch_bounds__(1024)
void scan_kernel(const int* __restrict__ cnt, int* __restrict__ offs,
                 int* __restrict__ cursor, int N) {
    __shared__ int sums[1024];
    int t = threadIdx.x;
    int per = (N + 1023) / 1024;
    int beg = t * per;
    int end = beg + per; if (end > N) end = N;
    int s = 0;
    for (int i = beg; i < end; i++) s += cnt[i];
    sums[t] = s;
    __syncthreads();
    for (int off = 1; off < 1024; off <<= 1) {
        int v = (t >= off) ? sums[t - off] : 0;
        __syncthreads();
        sums[t] += v;
        __syncthreads();
    }
    int run = (t == 0) ? 0 : sums[t - 1];
    for (int i = beg; i < end; i++) {
        offs[i] = run;
        cursor[i] = run;
        run += cnt[i];
    }
    if (t == 1023) offs[N] = sums[1023];
}
__global__ void scatter_kernel(const int* __restrict__ row, const int* __restrict__ col,
                               const float* __restrict__ ev,
                               int* __restrict__ cursor,
                               int* __restrict__ cols, float* __restrict__ evs, int E) {
    int e = blockIdx.x * blockDim.x + threadIdx.x;
    if (e >= E) return;
    int p = atomicAdd(cursor + __ldg(row + e), 1);
    cols[p] = __ldg(col + e);
    evs[p] = __ldg(ev + e);
}

// ---------------- fused edge gather + normalize + activation/skip ----------------
__global__ __launch_bounds__(256)
void edge_csr_kernel(const int* __restrict__ offs, const int* __restrict__ cols,
                     const float* __restrict__ evs,
                     const float* __restrict__ asrc, const float* __restrict__ adst,
                     const float* __restrict__ hfeat,
                     const float* __restrict__ skip, float* __restrict__ out,
                     int N, int mode) {
    int gwid = (blockIdx.x * blockDim.x + threadIdx.x) >> 5;
    if (gwid >= N) return;
    int lane = threadIdx.x & 31;
    int head = lane >> 2;

    float asr = __ldg(asrc + gwid * H + head);
    int beg = __ldg(offs + gwid);
    int end = __ldg(offs + gwid + 1);

    float ax = 0.f, ay = 0.f, az = 0.f, aw = 0.f, wsum = 0.f;

    int e = beg;
#pragma unroll 1
    for (; e + 3 < end; e += 4) {
        int c[4]; float v[4], dd[4]; float4 hh[4];
#pragma unroll
        for (int q = 0; q < 4; q++) {
            c[q] = __ldg(cols + e + q);
            v[q] = __ldg(evs + e + q);
        }
#pragma unroll
        for (int q = 0; q < 4; q++) {
            dd[q] = __ldg(adst + c[q] * H + head);
            hh[q] = *(const float4*)(hfeat + (size_t)c[q] * F + lane * 4);
        }
#pragma unroll
        for (int q = 0; q < 4; q++) {
            float lg = v[q] * (asr + dd[q]);
            lg = fmaxf(lg, 0.2f * lg);
            float wgt = __expf(lg);
            ax += wgt * hh[q].x; ay += wgt * hh[q].y;
            az += wgt * hh[q].z; aw += wgt * hh[q].w;
            wsum += wgt;
        }
    }
#pragma unroll 1
    for (; e < end; e++) {
        int   c0 = __ldg(cols + e);
        float v0 = __ldg(evs + e);
        float d0 = __ldg(adst + c0 * H + head);
        float4 h0 = *(const float4*)(hfeat + (size_t)c0 * F + lane * 4);
        float l0 = v0 * (asr + d0);
        l0 = fmaxf(l0, 0.2f * l0);
        float w0 = __expf(l0);
        ax += w0 * h0.x; ay += w0 * h0.y; az += w0 * h0.z; aw += w0 * h0.w;
        wsum += w0;
    }

    float inv = 1.0f / wsum;
    float4 v;
    v.x = ax * inv; v.y = ay * inv; v.z = az * inv; v.w = aw * inv;
    if (mode == 0) {
        v.x = (v.x > 0.f) ? v.x : expm1f(v.x);
        v.y = (v.y > 0.f) ? v.y : expm1f(v.y);
        v.z = (v.z > 0.f) ? v.z : expm1f(v.z);
        v.w = (v.w > 0.f) ? v.w : expm1f(v.w);
    } else {
        float4 sk = *(const float4*)(skip + (size_t)gwid * F + lane * 4);
        v.x += sk.x; v.y += sk.y; v.z += sk.z; v.w += sk.w;
    }
    *(float4*)(out + (size_t)gwid * F + lane * 4) = v;
}

// ---------------- launch ----------------
extern "C" void kernel_launch(void* const* d_in, const int* in_sizes, int n_in,
                              void* d_out, int out_size) {
    const float* x    = (const float*)d_in[0];
    const int*   eidx = (const int*)  d_in[1];
    const float* ev   = (const float*)d_in[2];
    const float* encW = (const float*)d_in[3];
    const float* encb = (const float*)d_in[4];
    const float* Wst  = (const float*)d_in[5];
    const float* ast  = (const float*)d_in[6];
    float* out = (float*)d_out;

    int N = in_sizes[0] / F;
    int E = in_sizes[2];
    const int* row  = eidx;
    const int* colp = eidx + E;

    float *xc, *hbuf, *asrc, *adst, *evs;
    int *cnt, *offs, *cursor, *cols;
    __nv_bfloat16 *Bhi, *Blo;
    cudaGetSymbolAddress((void**)&xc,     g_xc);
    cudaGetSymbolAddress((void**)&hbuf,   g_h);
    cudaGetSymbolAddress((void**)&asrc,   g_asrc);
    cudaGetSymbolAddress((void**)&adst,   g_adst);
    cudaGetSymbolAddress((void**)&cnt,    g_cnt);
    cudaGetSymbolAddress((void**)&offs,   g_offs);
    cudaGetSymbolAddress((void**)&cursor, g_cursor);
    cudaGetSymbolAddress((void**)&cols,   g_cols);
    cudaGetSymbolAddress((void**)&evs,    g_evs);
    cudaGetSymbolAddress((void**)&Bhi,    g_Bhi);
    cudaGetSymbolAddress((void**)&Blo,    g_Blo);

    static int smem_set = 0;
    if (!smem_set) {
        cudaFuncSetAttribute(mma_gemm_kernel,
                             cudaFuncAttributeMaxDynamicSharedMemorySize, SMEM_TOT);
        smem_set = 1;
    }

    const int TB = 256;
    int gemm_blocks = (N + 127) / 128;
    int edge_blocks = (N * 32 + TB - 1) / TB;

    // ---- CSR build + weight prep ----
    zero_cnt_kernel<<<(N + TB - 1) / TB, TB>>>(cnt, N);
    hist_kernel<<<(E + TB - 1) / TB, TB>>>(row, cnt, E);
    prepB_kernel<<<(3 * F * STR + TB - 1) / TB, TB>>>(encW, Wst);
    scan_kernel<<<1, 1024>>>(cnt, offs, cursor, N);
    scatter_kernel<<<(E + TB - 1) / TB, TB>>>(row, colp, ev, cursor, cols, evs, E);

    // ---- encoder: xc = x @ enc_W + enc_b ----
    mma_gemm_kernel<<<gemm_blocks, 256, SMEM_TOT>>>(x, Bhi, Blo, encb, xc,
                                                    nullptr, nullptr, nullptr, N);

    for (int ell = 0; ell < 2; ell++) {
        const float* al = ast + ell * H * 2 * DH;
        const __nv_bfloat16* bh = Bhi + (1 + ell) * F * STR;
        const __nv_bfloat16* bl = Blo + (1 + ell) * F * STR;

        mma_gemm_kernel<<<gemm_blocks, 256, SMEM_TOT>>>(xc, bh, bl, nullptr, hbuf,
                                                        al, asrc, adst, N);

        if (ell == 0) {
            edge_csr_kernel<<<edge_blocks, TB>>>(offs, cols, evs, asrc, adst, hbuf,
                                                 nullptr, xc, N, 0);
        } else {
            edge_csr_kernel<<<edge_blocks, TB>>>(offs, cols, evs, asrc, adst, hbuf,
                                                 xc, out, N, 1);
        }
    }
}

// round 7
// speedup vs baseline: 2.5893x; 1.3092x over previous
#include <cuda_runtime.h>
#include <cuda_bf16.h>
#include <cstdint>

#define F     128      // HID == F_IN
#define H     8        // heads
#define DH    16       // dim per head
#define NMAX  65536
#define EMAX  1000000
#define SCAN_B 1024
#define MAXBLK 64      // max scan blocks (ceil(NMAX/1024))

#define STR   136                       // padded bf16 row stride (272 B)
#define A_HI  0
#define A_LO  (128 * STR * 2)           // 34816
#define B_HI  (2 * 128 * STR * 2)       // 69632
#define B_LO  (3 * 128 * STR * 2)       // 104448
#define SMEM_TOT (4 * 128 * STR * 2)    // 139264

// ---------------- device scratch (no allocations allowed) ----------------
__device__ __align__(16) float g_xc[NMAX * F];
__device__ __align__(16) float g_h[NMAX * F];
__device__ __align__(16) float g_asrc[NMAX * H];
__device__ __align__(16) float g_adst[NMAX * H];
__device__ int   g_cnt[NMAX];
__device__ int   g_excl[NMAX];          // per-block exclusive scan values
__device__ int   g_bsum[MAXBLK];        // block totals
__device__ int   g_boff[MAXBLK];        // scanned block offsets
__device__ int   g_offs[NMAX + 1];
__device__ int   g_cursor[NMAX];
__device__ int   g_cols[EMAX];
__device__ float g_evs[EMAX];
// prepped weights: B^T [n][k] padded to STR, hi/lo bf16, 3 matrices
__device__ __align__(16) __nv_bfloat16 g_Bhi[3 * F * STR];
__device__ __align__(16) __nv_bfloat16 g_Blo[3 * F * STR];

// ---------------- helpers ----------------
__device__ __forceinline__ uint32_t smem_u32(const void* p) {
    uint32_t a;
    asm("{ .reg .u64 t; cvta.to.shared.u64 t, %1; cvt.u32.u64 %0, t; }" : "=r"(a) : "l"(p));
    return a;
}
__device__ __forceinline__ void ldx4(uint32_t* r, uint32_t addr) {
    asm volatile("ldmatrix.sync.aligned.m8n8.x4.shared.b16 {%0,%1,%2,%3}, [%4];"
                 : "=r"(r[0]), "=r"(r[1]), "=r"(r[2]), "=r"(r[3]) : "r"(addr));
}
__device__ __forceinline__ void mma_bf16(float* c, const uint32_t* a, uint32_t b0, uint32_t b1) {
    asm volatile("mma.sync.aligned.m16n8k16.row.col.f32.bf16.bf16.f32 "
                 "{%0,%1,%2,%3}, {%4,%5,%6,%7}, {%8,%9}, {%0,%1,%2,%3};"
                 : "+f"(c[0]), "+f"(c[1]), "+f"(c[2]), "+f"(c[3])
                 : "r"(a[0]), "r"(a[1]), "r"(a[2]), "r"(a[3]), "r"(b0), "r"(b1));
}

// ---------------- weight prep: W[k][n] -> B^T[n][k] padded, hi/lo bf16 ----------------
__global__ void prepB_kernel(const float* __restrict__ encW,
                             const float* __restrict__ Wst) {
    int idx = blockIdx.x * blockDim.x + threadIdx.x;
    if (idx >= 3 * F * STR) return;
    int mat = idx / (F * STR);
    int t = idx % (F * STR);
    int n = t / STR, k = t % STR;
    float w = 0.f;
    if (k < F) {
        if (mat == 0) w = encW[k * F + n];
        else {
            int hh = n >> 4, f = n & 15;
            w = Wst[(mat - 1) * (H * F * DH) + (hh * F + k) * DH + f];
        }
    }
    __nv_bfloat16 hi = __float2bfloat16(w);
    __nv_bfloat16 lo = __float2bfloat16(w - __bfloat162float(hi));
    g_Bhi[idx] = hi;
    g_Blo[idx] = lo;
}

// ---------------- HMMA GEMM: C[N,128] = A[N,128] @ W (+bias), fused alpha ----------------
__global__ __launch_bounds__(256)
void mma_gemm_kernel(const float* __restrict__ A,
                     const __nv_bfloat16* __restrict__ Bhi,
                     const __nv_bfloat16* __restrict__ Blo,
                     const float* __restrict__ bias, float* __restrict__ C,
                     const float* __restrict__ avec,
                     float* __restrict__ asrc, float* __restrict__ adst, int Nrows) {
    extern __shared__ char smem[];
    uint32_t sb = smem_u32(smem);
    int tid = threadIdx.x;
    int l = tid & 31, w = tid >> 5;
    int row0 = blockIdx.x * 128;

    // ---- stage A: 128x128 f32 -> hi/lo bf16, padded rows ----
#pragma unroll
    for (int it = 0; it < 16; it++) {
        int g = tid + it * 256;
        int r = g >> 5;
        int kq = (g & 31) * 4;
        float4 v = make_float4(0.f, 0.f, 0.f, 0.f);
        if (row0 + r < Nrows) v = *(const float4*)(A + (size_t)(row0 + r) * F + kq);
        __nv_bfloat16 h0 = __float2bfloat16(v.x), h1 = __float2bfloat16(v.y);
        __nv_bfloat16 h2 = __float2bfloat16(v.z), h3 = __float2bfloat16(v.w);
        __nv_bfloat16 l0 = __float2bfloat16(v.x - __bfloat162float(h0));
        __nv_bfloat16 l1 = __float2bfloat16(v.y - __bfloat162float(h1));
        __nv_bfloat16 l2 = __float2bfloat16(v.z - __bfloat162float(h2));
        __nv_bfloat16 l3 = __float2bfloat16(v.w - __bfloat162float(h3));
        uint32_t off = (uint32_t)r * 272u + (uint32_t)kq * 2u;
        __nv_bfloat162 hp0 = {h0, h1}, hp1 = {h2, h3};
        __nv_bfloat162 lp0 = {l0, l1}, lp1 = {l2, l3};
        *(uint2*)(smem + A_HI + off) = make_uint2(*(uint32_t*)&hp0, *(uint32_t*)&hp1);
        *(uint2*)(smem + A_LO + off) = make_uint2(*(uint32_t*)&lp0, *(uint32_t*)&lp1);
    }
    // ---- copy prepped B^T hi/lo (34816 B each = 2176 uint4) ----
    for (int i = tid; i < 2176; i += 256) {
        ((uint4*)(smem + B_HI))[i] = ((const uint4*)Bhi)[i];
        ((uint4*)(smem + B_LO))[i] = ((const uint4*)Blo)[i];
    }
    __syncthreads();

    int wr = w >> 1, wc = w & 1;
    int lt = l & 7, lg = l >> 3;

    uint32_t aoff[2];
#pragma unroll
    for (int i = 0; i < 2; i++)
        aoff[i] = (uint32_t)(wr * 32 + i * 16 + lt + (lg & 1) * 8) * 272u + (uint32_t)(lg >> 1) * 16u;
    uint32_t boff[4];
#pragma unroll
    for (int p = 0; p < 4; p++)
        boff[p] = (uint32_t)(wc * 64 + 8 * (2 * p + (lg >> 1)) + lt) * 272u + (uint32_t)(lg & 1) * 16u;

    float c[2][8][4];
#pragma unroll
    for (int i = 0; i < 2; i++)
#pragma unroll
        for (int j = 0; j < 8; j++)
#pragma unroll
            for (int q = 0; q < 4; q++) c[i][j][q] = 0.f;

    uint32_t ah[2][4], al[2][4], b[4][4];

#pragma unroll
    for (int ks = 0; ks < 8; ks++) {
        uint32_t k2 = (uint32_t)ks * 32u;
        ldx4(ah[0], sb + A_HI + aoff[0] + k2);
        ldx4(ah[1], sb + A_HI + aoff[1] + k2);
        ldx4(al[0], sb + A_LO + aoff[0] + k2);
        ldx4(al[1], sb + A_LO + aoff[1] + k2);
#pragma unroll
        for (int p = 0; p < 4; p++) ldx4(b[p], sb + B_HI + boff[p] + k2);
#pragma unroll
        for (int i = 0; i < 2; i++)
#pragma unroll
            for (int p = 0; p < 4; p++) {
                mma_bf16(c[i][2 * p],     ah[i], b[p][0], b[p][1]);
                mma_bf16(c[i][2 * p + 1], ah[i], b[p][2], b[p][3]);
                mma_bf16(c[i][2 * p],     al[i], b[p][0], b[p][1]);
                mma_bf16(c[i][2 * p + 1], al[i], b[p][2], b[p][3]);
            }
#pragma unroll
        for (int p = 0; p < 4; p++) ldx4(b[p], sb + B_LO + boff[p] + k2);
#pragma unroll
        for (int i = 0; i < 2; i++)
#pragma unroll
            for (int p = 0; p < 4; p++) {
                mma_bf16(c[i][2 * p],     ah[i], b[p][0], b[p][1]);
                mma_bf16(c[i][2 * p + 1], ah[i], b[p][2], b[p][3]);
            }
    }

    // ---- epilogue: store C (+bias), fused alpha ----
#pragma unroll
    for (int i = 0; i < 2; i++) {
#pragma unroll
        for (int rh = 0; rh < 2; rh++) {
            int row = row0 + wr * 32 + i * 16 + rh * 8 + (l >> 2);
            bool valid = (row < Nrows);
            if (valid) {
#pragma unroll
                for (int j = 0; j < 8; j++) {
                    int col = wc * 64 + 8 * j + 2 * (l & 3);
                    float v0 = c[i][j][2 * rh], v1 = c[i][j][2 * rh + 1];
                    if (bias) { v0 += __ldg(bias + col); v1 += __ldg(bias + col + 1); }
                    float2 st; st.x = v0; st.y = v1;
                    *(float2*)(C + (size_t)row * F + col) = st;
                }
            }
            if (avec) {
                float s[4], d[4];
#pragma unroll
                for (int q = 0; q < 4; q++) { s[q] = 0.f; d[q] = 0.f; }
#pragma unroll
                for (int j = 0; j < 8; j++) {
                    int hl = j >> 1;
                    int hh = 4 * wc + hl;
                    int f0 = 8 * (j & 1) + 2 * (l & 3);
                    float v0 = c[i][j][2 * rh], v1 = c[i][j][2 * rh + 1];
                    s[hl] += v0 * __ldg(avec + hh * 32 + f0) + v1 * __ldg(avec + hh * 32 + f0 + 1);
                    d[hl] += v0 * __ldg(avec + hh * 32 + 16 + f0) + v1 * __ldg(avec + hh * 32 + 16 + f0 + 1);
                }
#pragma unroll
                for (int q = 0; q < 4; q++) {
                    s[q] += __shfl_xor_sync(0xffffffffu, s[q], 1);
                    s[q] += __shfl_xor_sync(0xffffffffu, s[q], 2);
                    d[q] += __shfl_xor_sync(0xffffffffu, d[q], 1);
                    d[q] += __shfl_xor_sync(0xffffffffu, d[q], 2);
                }
                if ((l & 3) == 0 && valid) {
#pragma unroll
                    for (int q = 0; q < 4; q++) {
                        asrc[row * H + 4 * wc + q] = s[q];
                        adst[row * H + 4 * wc + q] = d[q];
                    }
                }
            }
        }
    }
}

// ---------------- CSR construction ----------------
__global__ void zero_cnt_kernel(int* __restrict__ cnt, int N) {
    int i = blockIdx.x * blockDim.x + threadIdx.x;
    if (i < N) cnt[i] = 0;
}
__global__ void hist_kernel(const int* __restrict__ row, int* __restrict__ cnt, int E) {
    int e = blockIdx.x * blockDim.x + threadIdx.x;
    if (e < E) atomicAdd(cnt + __ldg(row + e), 1);
}

// phase 1: per-block exclusive scan + block totals
__global__ __launch_bounds__(SCAN_B)
void blockscan_kernel(const int* __restrict__ cnt, int* __restrict__ excl,
                      int* __restrict__ bsum, int N) {
    __shared__ int sh[SCAN_B];
    int t = threadIdx.x;
    int i = blockIdx.x * SCAN_B + t;
    int v = (i < N) ? cnt[i] : 0;
    sh[t] = v;
    __syncthreads();
    int run = v;
    for (int off = 1; off < SCAN_B; off <<= 1) {
        int u = (t >= off) ? sh[t - off] : 0;
        __syncthreads();
        run += u;
        sh[t] = run;
        __syncthreads();
    }
    if (i < N) excl[i] = run - v;              // exclusive within block
    if (t == SCAN_B - 1) bsum[blockIdx.x] = run;
}

// phase 2: exclusive scan of block totals (<= MAXBLK values, 1 warp-ish block)
__global__ void scan_bsums_kernel(const int* __restrict__ bsum, int* __restrict__ boff,
                                  int nb) {
    __shared__ int sh[MAXBLK];
    int t = threadIdx.x;
    int v = (t < nb) ? bsum[t] : 0;
    sh[t] = v;
    __syncthreads();
    int run = v;
    for (int off = 1; off < MAXBLK; off <<= 1) {
        int u = (t >= off) ? sh[t - off] : 0;
        __syncthreads();
        run += u;
        sh[t] = run;
        __syncthreads();
    }
    if (t < nb) boff[t] = run - v;             // exclusive
}

// phase 3: apply block offsets, emit offs + cursor (+ offs[N] = E)
__global__ void apply_scan_kernel(const int* __restrict__ excl, const int* __restrict__ boff,
                                  int* __restrict__ offs, int* __restrict__ cursor,
                                  int N, int E) {
    int i = blockIdx.x * blockDim.x + threadIdx.x;
    if (i < N) {
        int v = excl[i] + boff[i / SCAN_B];
        offs[i] = v;
        cursor[i] = v;
    }
    if (i == 0) offs[N] = E;
}

__global__ void scatter_kernel(const int* __restrict__ row, const int* __restrict__ col,
                               const float* __restrict__ ev,
                               int* __restrict__ cursor,
                               int* __restrict__ cols, float* __restrict__ evs, int E) {
    int e = blockIdx.x * blockDim.x + threadIdx.x;
    if (e >= E) return;
    int p = atomicAdd(cursor + __ldg(row + e), 1);
    cols[p] = __ldg(col + e);
    evs[p] = __ldg(ev + e);
}

// ---------------- fused edge gather + normalize + activation/skip ----------------
__global__ __launch_bounds__(256)
void edge_csr_kernel(const int* __restrict__ offs, const int* __restrict__ cols,
                     const float* __restrict__ evs,
                     const float* __restrict__ asrc, const float* __restrict__ adst,
                     const float* __restrict__ hfeat,
                     const float* __restrict__ skip, float* __restrict__ out,
                     int N, int mode) {
    int gwid = (blockIdx.x * blockDim.x + threadIdx.x) >> 5;
    if (gwid >= N) return;
    int lane = threadIdx.x & 31;
    int head = lane >> 2;

    float asr = __ldg(asrc + gwid * H + head);
    int beg = __ldg(offs + gwid);
    int end = __ldg(offs + gwid + 1);

    float ax = 0.f, ay = 0.f, az = 0.f, aw = 0.f, wsum = 0.f;

    int e = beg;
#pragma unroll 1
    for (; e + 3 < end; e += 4) {
        int c[4]; float v[4], dd[4]; float4 hh[4];
#pragma unroll
        for (int q = 0; q < 4; q++) {
            c[q] = __ldg(cols + e + q);
            v[q] = __ldg(evs + e + q);
        }
#pragma unroll
        for (int q = 0; q < 4; q++) {
            dd[q] = __ldg(adst + c[q] * H + head);
            hh[q] = *(const float4*)(hfeat + (size_t)c[q] * F + lane * 4);
        }
#pragma unroll
        for (int q = 0; q < 4; q++) {
            float lg = v[q] * (asr + dd[q]);
            lg = fmaxf(lg, 0.2f * lg);
            float wgt = __expf(lg);
            ax += wgt * hh[q].x; ay += wgt * hh[q].y;
            az += wgt * hh[q].z; aw += wgt * hh[q].w;
            wsum += wgt;
        }
    }
#pragma unroll 1
    for (; e < end; e++) {
        int   c0 = __ldg(cols + e);
        float v0 = __ldg(evs + e);
        float d0 = __ldg(adst + c0 * H + head);
        float4 h0 = *(const float4*)(hfeat + (size_t)c0 * F + lane * 4);
        float l0 = v0 * (asr + d0);
        l0 = fmaxf(l0, 0.2f * l0);
        float w0 = __expf(l0);
        ax += w0 * h0.x; ay += w0 * h0.y; az += w0 * h0.z; aw += w0 * h0.w;
        wsum += w0;
    }

    float inv = 1.0f / wsum;
    float4 v;
    v.x = ax * inv; v.y = ay * inv; v.z = az * inv; v.w = aw * inv;
    if (mode == 0) {
        v.x = (v.x > 0.f) ? v.x : expm1f(v.x);
        v.y = (v.y > 0.f) ? v.y : expm1f(v.y);
        v.z = (v.z > 0.f) ? v.z : expm1f(v.z);
        v.w = (v.w > 0.f) ? v.w : expm1f(v.w);
    } else {
        float4 sk = *(const float4*)(skip + (size_t)gwid * F + lane * 4);
        v.x += sk.x; v.y += sk.y; v.z += sk.z; v.w += sk.w;
    }
    *(float4*)(out + (size_t)gwid * F + lane * 4) = v;
}

// ---------------- launch ----------------
extern "C" void kernel_launch(void* const* d_in, const int* in_sizes, int n_in,
                              void* d_out, int out_size) {
    const float* x    = (const float*)d_in[0];
    const int*   eidx = (const int*)  d_in[1];
    const float* ev   = (const float*)d_in[2];
    const float* encW = (const float*)d_in[3];
    const float* encb = (const float*)d_in[4];
    const float* Wst  = (const float*)d_in[5];
    const float* ast  = (const float*)d_in[6];
    float* out = (float*)d_out;

    int N = in_sizes[0] / F;
    int E = in_sizes[2];
    const int* row  = eidx;
    const int* colp = eidx + E;

    float *xc, *hbuf, *asrc, *adst, *evs;
    int *cnt, *excl, *bsum, *bo, *offs, *cursor, *cols;
    __nv_bfloat16 *Bhi, *Blo;
    cudaGetSymbolAddress((void**)&xc,     g_xc);
    cudaGetSymbolAddress((void**)&hbuf,   g_h);
    cudaGetSymbolAddress((void**)&asrc,   g_asrc);
    cudaGetSymbolAddress((void**)&adst,   g_adst);
    cudaGetSymbolAddress((void**)&cnt,    g_cnt);
    cudaGetSymbolAddress((void**)&excl,   g_excl);
    cudaGetSymbolAddress((void**)&bsum,   g_bsum);
    cudaGetSymbolAddress((void**)&bo,     g_boff);
    cudaGetSymbolAddress((void**)&offs,   g_offs);
    cudaGetSymbolAddress((void**)&cursor, g_cursor);
    cudaGetSymbolAddress((void**)&cols,   g_cols);
    cudaGetSymbolAddress((void**)&evs,    g_evs);
    cudaGetSymbolAddress((void**)&Bhi,    g_Bhi);
    cudaGetSymbolAddress((void**)&Blo,    g_Blo);

    static int smem_set = 0;
    if (!smem_set) {
        cudaFuncSetAttribute(mma_gemm_kernel,
                             cudaFuncAttributeMaxDynamicSharedMemorySize, SMEM_TOT);
        smem_set = 1;
    }

    const int TB = 256;
    int gemm_blocks = (N + 127) / 128;
    int edge_blocks = (N * 32 + TB - 1) / TB;
    int scan_blocks = (N + SCAN_B - 1) / SCAN_B;

    // ---- CSR build + weight prep ----
    zero_cnt_kernel<<<(N + TB - 1) / TB, TB>>>(cnt, N);
    hist_kernel<<<(E + TB - 1) / TB, TB>>>(row, cnt, E);
    prepB_kernel<<<(3 * F * STR + TB - 1) / TB, TB>>>(encW, Wst);
    blockscan_kernel<<<scan_blocks, SCAN_B>>>(cnt, excl, bsum, N);
    scan_bsums_kernel<<<1, MAXBLK>>>(bsum, bo, scan_blocks);
    apply_scan_kernel<<<(N + TB - 1) / TB, TB>>>(excl, bo, offs, cursor, N, E);
    scatter_kernel<<<(E + TB - 1) / TB, TB>>>(row, colp, ev, cursor, cols, evs, E);

    // ---- encoder: xc = x @ enc_W + enc_b ----
    mma_gemm_kernel<<<gemm_blocks, 256, SMEM_TOT>>>(x, Bhi, Blo, encb, xc,
                                                    nullptr, nullptr, nullptr, N);

    for (int ell = 0; ell < 2; ell++) {
        const float* al = ast + ell * H * 2 * DH;
        const __nv_bfloat16* bh = Bhi + (1 + ell) * F * STR;
        const __nv_bfloat16* bl = Blo + (1 + ell) * F * STR;

        mma_gemm_kernel<<<gemm_blocks, 256, SMEM_TOT>>>(xc, bh, bl, nullptr, hbuf,
                                                        al, asrc, adst, N);

        if (ell == 0) {
            edge_csr_kernel<<<edge_blocks, TB>>>(offs, cols, evs, asrc, adst, hbuf,
                                                 nullptr, xc, N, 0);
        } else {
            edge_csr_kernel<<<edge_blocks, TB>>>(offs, cols, evs, asrc, adst, hbuf,
                                                 xc, out, N, 1);
        }
    }
}

// round 8
// speedup vs baseline: 2.5897x; 1.0002x over previous
#include <cuda_runtime.h>
#include <cuda_bf16.h>
#include <cuda_fp16.h>
#include <cstdint>

#define F     128      // HID == F_IN
#define H     8        // heads
#define DH    16       // dim per head
#define NMAX  65536
#define EMAX  1000000
#define SCAN_B 1024
#define MAXBLK 64      // max scan blocks (ceil(NMAX/1024))

#define STR   136                       // padded bf16 row stride (272 B)
#define A_HI  0
#define A_LO  (128 * STR * 2)           // 34816
#define B_HI  (2 * 128 * STR * 2)       // 69632
#define B_LO  (3 * 128 * STR * 2)       // 104448
#define SMEM_TOT (4 * 128 * STR * 2)    // 139264

// ---------------- device scratch (no allocations allowed) ----------------
__device__ __align__(16) float  g_xc[NMAX * F];
__device__ __align__(16) __half g_h16[NMAX * F];     // fp16 projected features
__device__ __align__(16) float  g_asrc[NMAX * H];
__device__ __align__(16) float  g_adst[NMAX * H];
__device__ int   g_cnt[NMAX];
__device__ int   g_excl[NMAX];
__device__ int   g_bsum[MAXBLK];
__device__ int   g_offs[NMAX + 1];
__device__ int   g_cursor[NMAX];
__device__ __align__(16) int2 g_ecomb[EMAX];         // packed (col, ev-bits)
// prepped weights: B^T [n][k] padded to STR, hi/lo bf16, 3 matrices
__device__ __align__(16) __nv_bfloat16 g_Bhi[3 * F * STR];
__device__ __align__(16) __nv_bfloat16 g_Blo[3 * F * STR];

// ---------------- helpers ----------------
__device__ __forceinline__ uint32_t smem_u32(const void* p) {
    uint32_t a;
    asm("{ .reg .u64 t; cvta.to.shared.u64 t, %1; cvt.u32.u64 %0, t; }" : "=r"(a) : "l"(p));
    return a;
}
__device__ __forceinline__ void ldx4(uint32_t* r, uint32_t addr) {
    asm volatile("ldmatrix.sync.aligned.m8n8.x4.shared.b16 {%0,%1,%2,%3}, [%4];"
                 : "=r"(r[0]), "=r"(r[1]), "=r"(r[2]), "=r"(r[3]) : "r"(addr));
}
__device__ __forceinline__ void mma_bf16(float* c, const uint32_t* a, uint32_t b0, uint32_t b1) {
    asm volatile("mma.sync.aligned.m16n8k16.row.col.f32.bf16.bf16.f32 "
                 "{%0,%1,%2,%3}, {%4,%5,%6,%7}, {%8,%9}, {%0,%1,%2,%3};"
                 : "+f"(c[0]), "+f"(c[1]), "+f"(c[2]), "+f"(c[3])
                 : "r"(a[0]), "r"(a[1]), "r"(a[2]), "r"(a[3]), "r"(b0), "r"(b1));
}

// ---------------- weight prep: W[k][n] -> B^T[n][k] padded, hi/lo bf16 ----------------
__global__ void prepB_kernel(const float* __restrict__ encW,
                             const float* __restrict__ Wst) {
    int idx = blockIdx.x * blockDim.x + threadIdx.x;
    if (idx >= 3 * F * STR) return;
    int mat = idx / (F * STR);
    int t = idx % (F * STR);
    int n = t / STR, k = t % STR;
    float w = 0.f;
    if (k < F) {
        if (mat == 0) w = encW[k * F + n];
        else {
            int hh = n >> 4, f = n & 15;
            w = Wst[(mat - 1) * (H * F * DH) + (hh * F + k) * DH + f];
        }
    }
    __nv_bfloat16 hi = __float2bfloat16(w);
    __nv_bfloat16 lo = __float2bfloat16(w - __bfloat162float(hi));
    g_Bhi[idx] = hi;
    g_Blo[idx] = lo;
}

// ---------------- HMMA GEMM: C = A @ W (+bias), f32 and/or fp16 out, fused alpha ----------------
__global__ __launch_bounds__(256)
void mma_gemm_kernel(const float* __restrict__ A,
                     const __nv_bfloat16* __restrict__ Bhi,
                     const __nv_bfloat16* __restrict__ Blo,
                     const float* __restrict__ bias, float* __restrict__ Cf32,
                     __half* __restrict__ C16,
                     const float* __restrict__ avec,
                     float* __restrict__ asrc, float* __restrict__ adst, int Nrows) {
    extern __shared__ char smem[];
    uint32_t sb = smem_u32(smem);
    int tid = threadIdx.x;
    int l = tid & 31, w = tid >> 5;
    int row0 = blockIdx.x * 128;

    // ---- stage A: 128x128 f32 -> hi/lo bf16, padded rows ----
#pragma unroll
    for (int it = 0; it < 16; it++) {
        int g = tid + it * 256;
        int r = g >> 5;
        int kq = (g & 31) * 4;
        float4 v = make_float4(0.f, 0.f, 0.f, 0.f);
        if (row0 + r < Nrows) v = *(const float4*)(A + (size_t)(row0 + r) * F + kq);
        __nv_bfloat16 h0 = __float2bfloat16(v.x), h1 = __float2bfloat16(v.y);
        __nv_bfloat16 h2 = __float2bfloat16(v.z), h3 = __float2bfloat16(v.w);
        __nv_bfloat16 l0 = __float2bfloat16(v.x - __bfloat162float(h0));
        __nv_bfloat16 l1 = __float2bfloat16(v.y - __bfloat162float(h1));
        __nv_bfloat16 l2 = __float2bfloat16(v.z - __bfloat162float(h2));
        __nv_bfloat16 l3 = __float2bfloat16(v.w - __bfloat162float(h3));
        uint32_t off = (uint32_t)r * 272u + (uint32_t)kq * 2u;
        __nv_bfloat162 hp0 = {h0, h1}, hp1 = {h2, h3};
        __nv_bfloat162 lp0 = {l0, l1}, lp1 = {l2, l3};
        *(uint2*)(smem + A_HI + off) = make_uint2(*(uint32_t*)&hp0, *(uint32_t*)&hp1);
        *(uint2*)(smem + A_LO + off) = make_uint2(*(uint32_t*)&lp0, *(uint32_t*)&lp1);
    }
    // ---- copy prepped B^T hi/lo (34816 B each = 2176 uint4) ----
    for (int i = tid; i < 2176; i += 256) {
        ((uint4*)(smem + B_HI))[i] = ((const uint4*)Bhi)[i];
        ((uint4*)(smem + B_LO))[i] = ((const uint4*)Blo)[i];
    }
    __syncthreads();

    int wr = w >> 1, wc = w & 1;
    int lt = l & 7, lg = l >> 3;

    uint32_t aoff[2];
#pragma unroll
    for (int i = 0; i < 2; i++)
        aoff[i] = (uint32_t)(wr * 32 + i * 16 + lt + (lg & 1) * 8) * 272u + (uint32_t)(lg >> 1) * 16u;
    uint32_t boff[4];
#pragma unroll
    for (int p = 0; p < 4; p++)
        boff[p] = (uint32_t)(wc * 64 + 8 * (2 * p + (lg >> 1)) + lt) * 272u + (uint32_t)(lg & 1) * 16u;

    float c[2][8][4];
#pragma unroll
    for (int i = 0; i < 2; i++)
#pragma unroll
        for (int j = 0; j < 8; j++)
#pragma unroll
            for (int q = 0; q < 4; q++) c[i][j][q] = 0.f;

    uint32_t ah[2][4], al[2][4], b[4][4];

#pragma unroll
    for (int ks = 0; ks < 8; ks++) {
        uint32_t k2 = (uint32_t)ks * 32u;
        ldx4(ah[0], sb + A_HI + aoff[0] + k2);
        ldx4(ah[1], sb + A_HI + aoff[1] + k2);
        ldx4(al[0], sb + A_LO + aoff[0] + k2);
        ldx4(al[1], sb + A_LO + aoff[1] + k2);
#pragma unroll
        for (int p = 0; p < 4; p++) ldx4(b[p], sb + B_HI + boff[p] + k2);
#pragma unroll
        for (int i = 0; i < 2; i++)
#pragma unroll
            for (int p = 0; p < 4; p++) {
                mma_bf16(c[i][2 * p],     ah[i], b[p][0], b[p][1]);
                mma_bf16(c[i][2 * p + 1], ah[i], b[p][2], b[p][3]);
                mma_bf16(c[i][2 * p],     al[i], b[p][0], b[p][1]);
                mma_bf16(c[i][2 * p + 1], al[i], b[p][2], b[p][3]);
            }
#pragma unroll
        for (int p = 0; p < 4; p++) ldx4(b[p], sb + B_LO + boff[p] + k2);
#pragma unroll
        for (int i = 0; i < 2; i++)
#pragma unroll
            for (int p = 0; p < 4; p++) {
                mma_bf16(c[i][2 * p],     ah[i], b[p][0], b[p][1]);
                mma_bf16(c[i][2 * p + 1], ah[i], b[p][2], b[p][3]);
            }
    }

    // ---- epilogue ----
#pragma unroll
    for (int i = 0; i < 2; i++) {
#pragma unroll
        for (int rh = 0; rh < 2; rh++) {
            int row = row0 + wr * 32 + i * 16 + rh * 8 + (l >> 2);
            bool valid = (row < Nrows);
            if (valid) {
#pragma unroll
                for (int j = 0; j < 8; j++) {
                    int col = wc * 64 + 8 * j + 2 * (l & 3);
                    float v0 = c[i][j][2 * rh], v1 = c[i][j][2 * rh + 1];
                    if (bias) { v0 += __ldg(bias + col); v1 += __ldg(bias + col + 1); }
                    if (Cf32) {
                        float2 st; st.x = v0; st.y = v1;
                        *(float2*)(Cf32 + (size_t)row * F + col) = st;
                    }
                    if (C16) {
                        *(__half2*)(C16 + (size_t)row * F + col) =
                            __float22half2_rn(make_float2(v0, v1));
                    }
                }
            }
            if (avec) {
                float s[4], d[4];
#pragma unroll
                for (int q = 0; q < 4; q++) { s[q] = 0.f; d[q] = 0.f; }
#pragma unroll
                for (int j = 0; j < 8; j++) {
                    int hl = j >> 1;
                    int hh = 4 * wc + hl;
                    int f0 = 8 * (j & 1) + 2 * (l & 3);
                    float v0 = c[i][j][2 * rh], v1 = c[i][j][2 * rh + 1];
                    s[hl] += v0 * __ldg(avec + hh * 32 + f0) + v1 * __ldg(avec + hh * 32 + f0 + 1);
                    d[hl] += v0 * __ldg(avec + hh * 32 + 16 + f0) + v1 * __ldg(avec + hh * 32 + 16 + f0 + 1);
                }
#pragma unroll
                for (int q = 0; q < 4; q++) {
                    s[q] += __shfl_xor_sync(0xffffffffu, s[q], 1);
                    s[q] += __shfl_xor_sync(0xffffffffu, s[q], 2);
                    d[q] += __shfl_xor_sync(0xffffffffu, d[q], 1);
                    d[q] += __shfl_xor_sync(0xffffffffu, d[q], 2);
                }
                if ((l & 3) == 0 && valid) {
#pragma unroll
                    for (int q = 0; q < 4; q++) {
                        asrc[row * H + 4 * wc + q] = s[q];
                        adst[row * H + 4 * wc + q] = d[q];
                    }
                }
            }
        }
    }
}

// ---------------- CSR construction ----------------
__global__ void zero_cnt_kernel(int* __restrict__ cnt, int N) {
    int i = blockIdx.x * blockDim.x + threadIdx.x;
    if (i < N) cnt[i] = 0;
}
__global__ void hist_kernel(const int* __restrict__ row, int* __restrict__ cnt, int E) {
    int e = blockIdx.x * blockDim.x + threadIdx.x;
    if (e < E) atomicAdd(cnt + __ldg(row + e), 1);
}

// phase 1: per-block exclusive scan + block totals
__global__ __launch_bounds__(SCAN_B)
void blockscan_kernel(const int* __restrict__ cnt, int* __restrict__ excl,
                      int* __restrict__ bsum, int N) {
    __shared__ int sh[SCAN_B];
    int t = threadIdx.x;
    int i = blockIdx.x * SCAN_B + t;
    int v = (i < N) ? cnt[i] : 0;
    sh[t] = v;
    __syncthreads();
    int run = v;
    for (int off = 1; off < SCAN_B; off <<= 1) {
        int u = (t >= off) ? sh[t - off] : 0;
        __syncthreads();
        run += u;
        sh[t] = run;
        __syncthreads();
    }
    if (i < N) excl[i] = run - v;
    if (t == SCAN_B - 1) bsum[blockIdx.x] = run;
}

// phase 2+3 fused: scan block totals, apply, emit offs + cursor
__global__ __launch_bounds__(SCAN_B)
void scan_apply_kernel(const int* __restrict__ bsum, const int* __restrict__ excl,
                       int* __restrict__ offs, int* __restrict__ cursor,
                       int nb, int N, int E) {
    __shared__ int sh[MAXBLK];
    int t = threadIdx.x;
    int v = (t < nb) ? bsum[t] : 0;
    if (t < MAXBLK) sh[t] = v;
    __syncthreads();
    int run = v;
    for (int off = 1; off < MAXBLK; off <<= 1) {
        int u = (t >= off && t < MAXBLK) ? sh[t - off] : 0;
        __syncthreads();
        if (t < MAXBLK) { run += u; sh[t] = run; }
        __syncthreads();
    }
    if (t < MAXBLK) sh[t] = run - v;     // exclusive block offset
    __syncthreads();
    for (int i = t; i < N; i += SCAN_B) {
        int val = excl[i] + sh[i >> 10];
        offs[i] = val;
        cursor[i] = val;
    }
    if (t == 0) offs[N] = E;
}

__global__ void scatter_kernel(const int* __restrict__ row, const int* __restrict__ col,
                               const float* __restrict__ ev,
                               int* __restrict__ cursor, int2* __restrict__ ecomb, int E) {
    int e = blockIdx.x * blockDim.x + threadIdx.x;
    if (e >= E) return;
    int p = atomicAdd(cursor + __ldg(row + e), 1);
    int2 pk;
    pk.x = __ldg(col + e);
    pk.y = __float_as_int(__ldg(ev + e));
    ecomb[p] = pk;
}

// ---------------- fused edge gather (fp16 h) + normalize + activation/skip ----------------
__global__ __launch_bounds__(256)
void edge_csr_kernel(const int* __restrict__ offs, const int2* __restrict__ ecomb,
                     const float* __restrict__ asrc, const float* __restrict__ adst,
                     const __half* __restrict__ h16,
                     const float* __restrict__ skip, float* __restrict__ out,
                     int N, int mode) {
    int gwid = (blockIdx.x * blockDim.x + threadIdx.x) >> 5;
    if (gwid >= N) return;
    int lane = threadIdx.x & 31;
    int head = lane >> 2;

    float asr = __ldg(asrc + gwid * H + head);
    int beg = __ldg(offs + gwid);
    int end = __ldg(offs + gwid + 1);

    float ax = 0.f, ay = 0.f, az = 0.f, aw = 0.f, wsum = 0.f;

    int e = beg;
#pragma unroll 1
    for (; e + 3 < end; e += 4) {
        int2 m[4]; float dd[4]; uint2 hh[4];
#pragma unroll
        for (int q = 0; q < 4; q++) m[q] = __ldg(ecomb + e + q);
#pragma unroll
        for (int q = 0; q < 4; q++) {
            dd[q] = __ldg(adst + m[q].x * H + head);
            hh[q] = *(const uint2*)(h16 + (size_t)m[q].x * F + lane * 4);
        }
#pragma unroll
        for (int q = 0; q < 4; q++) {
            float lg = __int_as_float(m[q].y) * (asr + dd[q]);
            lg = fmaxf(lg, 0.2f * lg);
            float wgt = __expf(lg);
            float2 f0 = __half22float2(*(const __half2*)&hh[q].x);
            float2 f1 = __half22float2(*(const __half2*)&hh[q].y);
            ax += wgt * f0.x; ay += wgt * f0.y;
            az += wgt * f1.x; aw += wgt * f1.y;
            wsum += wgt;
        }
    }
#pragma unroll 1
    for (; e < end; e++) {
        int2 m = __ldg(ecomb + e);
        float d0 = __ldg(adst + m.x * H + head);
        uint2 hh = *(const uint2*)(h16 + (size_t)m.x * F + lane * 4);
        float l0 = __int_as_float(m.y) * (asr + d0);
        l0 = fmaxf(l0, 0.2f * l0);
        float w0 = __expf(l0);
        float2 f0 = __half22float2(*(const __half2*)&hh.x);
        float2 f1 = __half22float2(*(const __half2*)&hh.y);
        ax += w0 * f0.x; ay += w0 * f0.y; az += w0 * f1.x; aw += w0 * f1.y;
        wsum += w0;
    }

    float inv = 1.0f / wsum;
    float4 v;
    v.x = ax * inv; v.y = ay * inv; v.z = az * inv; v.w = aw * inv;
    if (mode == 0) {
        v.x = (v.x > 0.f) ? v.x : expm1f(v.x);
        v.y = (v.y > 0.f) ? v.y : expm1f(v.y);
        v.z = (v.z > 0.f) ? v.z : expm1f(v.z);
        v.w = (v.w > 0.f) ? v.w : expm1f(v.w);
    } else {
        float4 sk = *(const float4*)(skip + (size_t)gwid * F + lane * 4);
        v.x += sk.x; v.y += sk.y; v.z += sk.z; v.w += sk.w;
    }
    *(float4*)(out + (size_t)gwid * F + lane * 4) = v;
}

// ---------------- launch ----------------
extern "C" void kernel_launch(void* const* d_in, const int* in_sizes, int n_in,
                              void* d_out, int out_size) {
    const float* x    = (const float*)d_in[0];
    const int*   eidx = (const int*)  d_in[1];
    const float* ev   = (const float*)d_in[2];
    const float* encW = (const float*)d_in[3];
    const float* encb = (const float*)d_in[4];
    const float* Wst  = (const float*)d_in[5];
    const float* ast  = (const float*)d_in[6];
    float* out = (float*)d_out;

    int N = in_sizes[0] / F;
    int E = in_sizes[2];
    const int* row  = eidx;
    const int* colp = eidx + E;

    float *xc, *asrc, *adst;
    __half* h16;
    int *cnt, *excl, *bsum, *offs, *cursor;
    int2* ecomb;
    __nv_bfloat16 *Bhi, *Blo;
    cudaGetSymbolAddress((void**)&xc,     g_xc);
    cudaGetSymbolAddress((void**)&h16,    g_h16);
    cudaGetSymbolAddress((void**)&asrc,   g_asrc);
    cudaGetSymbolAddress((void**)&adst,   g_adst);
    cudaGetSymbolAddress((void**)&cnt,    g_cnt);
    cudaGetSymbolAddress((void**)&excl,   g_excl);
    cudaGetSymbolAddress((void**)&bsum,   g_bsum);
    cudaGetSymbolAddress((void**)&offs,   g_offs);
    cudaGetSymbolAddress((void**)&cursor, g_cursor);
    cudaGetSymbolAddress((void**)&ecomb,  g_ecomb);
    cudaGetSymbolAddress((void**)&Bhi,    g_Bhi);
    cudaGetSymbolAddress((void**)&Blo,    g_Blo);

    static int smem_set = 0;
    if (!smem_set) {
        cudaFuncSetAttribute(mma_gemm_kernel,
                             cudaFuncAttributeMaxDynamicSharedMemorySize, SMEM_TOT);
        smem_set = 1;
    }

    const int TB = 256;
    int gemm_blocks = (N + 127) / 128;
    int edge_blocks = (N * 32 + TB - 1) / TB;
    int scan_blocks = (N + SCAN_B - 1) / SCAN_B;

    // ---- CSR build + weight prep ----
    zero_cnt_kernel<<<(N + TB - 1) / TB, TB>>>(cnt, N);
    hist_kernel<<<(E + TB - 1) / TB, TB>>>(row, cnt, E);
    prepB_kernel<<<(3 * F * STR + TB - 1) / TB, TB>>>(encW, Wst);
    blockscan_kernel<<<scan_blocks, SCAN_B>>>(cnt, excl, bsum, N);
    scan_apply_kernel<<<1, SCAN_B>>>(bsum, excl, offs, cursor, scan_blocks, N, E);
    scatter_kernel<<<(E + TB - 1) / TB, TB>>>(row, colp, ev, cursor, ecomb, E);

    // ---- encoder: xc = x @ enc_W + enc_b (f32 out) ----
    mma_gemm_kernel<<<gemm_blocks, 256, SMEM_TOT>>>(x, Bhi, Blo, encb, xc, nullptr,
                                                    nullptr, nullptr, nullptr, N);

    for (int ell = 0; ell < 2; ell++) {
        const float* al = ast + ell * H * 2 * DH;
        const __nv_bfloat16* bh = Bhi + (1 + ell) * F * STR;
        const __nv_bfloat16* bl = Blo + (1 + ell) * F * STR;

        // h16 = xc @ W (fp16 out), fused asrc/adst
        mma_gemm_kernel<<<gemm_blocks, 256, SMEM_TOT>>>(xc, bh, bl, nullptr, nullptr,
                                                        h16, al, asrc, adst, N);

        if (ell == 0) {
            edge_csr_kernel<<<edge_blocks, TB>>>(offs, ecomb, asrc, adst, h16,
                                                 nullptr, xc, N, 0);
        } else {
            edge_csr_kernel<<<edge_blocks, TB>>>(offs, ecomb, asrc, adst, h16,
                                                 xc, out, N, 1);
        }
    }
}